// round 15
// baseline (speedup 1.0000x reference)
#include <cuda_runtime.h>
#include <cuda_fp16.h>
#include <cstdint>

#define NB 256
#define HW 256
#define OFF_C1 512
#define OFF_C2 (512 + 16777216)

// half-stage slabs: U half 32KB + V half 16KB = 48KB; 4 buffers = 192KB
#define UH     32768
#define VH     16384
#define SLAB   49152
#define MBOFF  196608
#define SMEMG  196672

// ---------------- device scratch ----------------
__device__ uint4 g_X1[(size_t)NB * 64 * 512];    // [img][64 ch-chunk][256px][16] fp16
__device__ uint4 g_Y1[(size_t)NB * 64 * 512];
__device__ uint4 g_Y2[(size_t)NB * 32 * 512];
__device__ uint4 g_V [(size_t)NB * 64 * 2048];   // [img][icc][16t][64tile][32B]
__device__ uint4 g_U1[8 * 64 * 4096];            // [ocb][icc][16t][128oc][32B]
__device__ uint4 g_U2[4 * 64 * 4096];
__device__ float g_invn1[NB * HW];
__device__ float g_invn2[NB * HW];
__device__ float g_wclsT[512 * 512];

// ---------------- PTX helpers ----------------
__device__ __forceinline__ uint32_t smem_u32(const void* p) {
    uint32_t a;
    asm("{ .reg .u64 t; cvta.to.shared.u64 t, %1; cvt.u32.u64 %0, t; }" : "=r"(a) : "l"(p));
    return a;
}
#define MBAR_INIT(a, c)  asm volatile("mbarrier.init.shared.b64 [%0], %1;" :: "r"(a), "r"((uint32_t)(c)) : "memory")
#define MBAR_EXPECT_TX(a, n) \
    asm volatile("mbarrier.arrive.expect_tx.shared.b64 _, [%0], %1;" :: "r"(a), "r"((uint32_t)(n)) : "memory")
#define MBAR_WAIT(a, par) do {                                                    \
    uint32_t _m = (a), _p = (par), _d;                                            \
    asm volatile("{\n\t.reg .pred p;\n\t"                                         \
        "mbarrier.try_wait.parity.acquire.cta.shared::cta.b64 p, [%1], %2;\n\t"   \
        "selp.b32 %0,1,0,p;\n\t}" : "=r"(_d) : "r"(_m), "r"(_p) : "memory");      \
    if (!_d) {                                                                    \
        asm volatile("{\n\t.reg .pred P1;\n\tWL_%=:\n\t"                          \
            "mbarrier.try_wait.parity.acquire.cta.shared::cta.b64 P1, [%0], %1, 0x989680;\n\t" \
            "@P1 bra.uni WD_%=;\n\tbra.uni WL_%=;\n\tWD_%=:\n\t}"                 \
            :: "r"(_m), "r"(_p) : "memory");                                      \
    }                                                                             \
} while (0)
#define BULK_G2S(dst, src, bytes, bar) \
    asm volatile("cp.async.bulk.shared::cta.global.mbarrier::complete_tx::bytes [%0], [%1], %2, [%3];" \
        :: "r"(dst), "l"(src), "r"((uint32_t)(bytes)), "r"(bar) : "memory")
#define LDSM4(r0, r1, r2, r3, a) \
    asm volatile("ldmatrix.sync.aligned.m8n8.x4.shared.b16 {%0,%1,%2,%3}, [%4];" \
        : "=r"(r0), "=r"(r1), "=r"(r2), "=r"(r3) : "r"(a))
// in-place f16 HMMA: D = C = c (accumulate)
__device__ __forceinline__ void mma16816h(uint32_t* c, const uint32_t* a, uint32_t b0, uint32_t b1) {
    asm volatile(
        "mma.sync.aligned.m16n8k16.row.col.f16.f16.f16.f16 "
        "{%0,%1}, {%2,%3,%4,%5}, {%6,%7}, {%0,%1};\n"
        : "+r"(c[0]), "+r"(c[1])
        : "r"(a[0]), "r"(a[1]), "r"(a[2]), "r"(a[3]), "r"(b0), "r"(b1));
}
// D != C form (C = persistent zero regs)
__device__ __forceinline__ void mma16816h_z(uint32_t* d, const uint32_t* a, uint32_t b0, uint32_t b1,
                                            uint32_t z0, uint32_t z1) {
    asm volatile(
        "mma.sync.aligned.m16n8k16.row.col.f16.f16.f16.f16 "
        "{%0,%1}, {%2,%3,%4,%5}, {%6,%7}, {%8,%9};\n"
        : "=r"(d[0]), "=r"(d[1])
        : "r"(a[0]), "r"(a[1]), "r"(a[2]), "r"(a[3]), "r"(b0), "r"(b1), "r"(z0), "r"(z1));
}

// ---------------- K0: relu + channel norms + chunked fp16 layout ----------------
__global__ void k_norm(const float* __restrict__ f1, const float* __restrict__ f2,
                       __half* __restrict__ xin,
                       float* __restrict__ invn1, float* __restrict__ invn2) {
    int b = blockIdx.x, p = threadIdx.x;
    const float* f1b = f1 + (size_t)b * 65536;
    const float* f2b = f2 + (size_t)b * 65536;
    __half* xb = xin + (size_t)b * 64 * 4096;
    float s1 = 0.f, s2 = 0.f;
    for (int ch = 0; ch < 16; ++ch) {
        __half h1[16], h2[16];
        #pragma unroll
        for (int i = 0; i < 16; ++i) {
            float v1 = fmaxf(f1b[(ch * 16 + i) * HW + p], 0.f);
            float v2 = fmaxf(f2b[(ch * 16 + i) * HW + p], 0.f);
            s1 += v1 * v1;  s2 += v2 * v2;
            h1[i] = __float2half_rn(v1);
            h2[i] = __float2half_rn(v2);
        }
        *(uint4*)&xb[(size_t)ch * 4096 + p * 16]            = *(uint4*)&h1[0];
        *(uint4*)&xb[(size_t)ch * 4096 + p * 16 + 8]        = *(uint4*)&h1[8];
        *(uint4*)&xb[(size_t)(32 + ch) * 4096 + p * 16]     = *(uint4*)&h2[0];
        *(uint4*)&xb[(size_t)(32 + ch) * 4096 + p * 16 + 8] = *(uint4*)&h2[8];
    }
    invn1[b * HW + p] = 1.0f / fmaxf(sqrtf(s1), 1e-12f);
    invn2[b * HW + p] = 1.0f / fmaxf(sqrtf(s2), 1e-12f);
}

// ---------------- weight transform: U = G g G^T (ti=3 rows NEGATED) ----------------
__global__ void k_wtrans(const float* __restrict__ w, uint4* __restrict__ U,
                         int NICC) {
    extern __shared__ __align__(16) char su[];
    int ocb = blockIdx.x, icc = blockIdx.y, tid = threadIdx.x;
    #pragma unroll 1
    for (int k = 0; k < 8; ++k) {
        int pr = tid + 256 * k;               // 2048 (oc,ic) pairs
        int oc_l = pr >> 4, ic_l = pr & 15;
        int oc = ocb * 128 + oc_l;
        int ic = icc * 16 + ic_l;
        const float* gw = w + ((size_t)oc * 1024 + ic) * 9;
        float g00 = gw[0], g01 = gw[1], g02 = gw[2];
        float g10 = gw[3], g11 = gw[4], g12 = gw[5];
        float g20 = gw[6], g21 = gw[7], g22 = gw[8];
        float t0[3] = {g00, g01, g02};
        float t1[3] = {0.5f*(g00+g10+g20), 0.5f*(g01+g11+g21), 0.5f*(g02+g12+g22)};
        float t2[3] = {0.5f*(g00-g10+g20), 0.5f*(g01-g11+g21), 0.5f*(g02-g12+g22)};
        float t3[3] = {g20, g21, g22};
        float* tr[4] = {t0, t1, t2, t3};
        int sw = (oc_l >> 2) & 1;
        int phys = ((ic_l >> 3) ^ sw) * 16 + (ic_l & 7) * 2;
        #pragma unroll
        for (int i = 0; i < 4; ++i) {
            float* ti = tr[i];
            float sgn = (i == 3) ? -1.f : 1.f;     // bake A^T oy1 sign for ti=3
            float u0 = ti[0];
            float u1 = 0.5f * (ti[0] + ti[1] + ti[2]);
            float u2 = 0.5f * (ti[0] - ti[1] + ti[2]);
            float u3 = ti[2];
            float uv[4] = {u0, u1, u2, u3};
            #pragma unroll
            for (int j = 0; j < 4; ++j) {
                int t = i * 4 + j;
                *(__half*)(su + (t * 128 + oc_l) * 32 + phys) = __float2half_rn(sgn * uv[j]);
            }
        }
    }
    __syncthreads();
    uint4* dst = U + ((size_t)(ocb * NICC + icc)) * 4096;
    const uint4* s4 = (const uint4*)su;
    #pragma unroll 1
    for (int k = 0; k < 16; ++k) dst[tid + 256 * k] = s4[tid + 256 * k];
}

__global__ void k_prepcls(const float* __restrict__ w, float* __restrict__ o) {
    int idx = blockIdx.x * blockDim.x + threadIdx.x;
    if (idx >= 512 * 512) return;
    int ic = idx >> 9, oc = idx & 511;
    o[idx] = w[oc * 512 + ic];
}

// ---------------- K1: correlation GEMM (fp32 outputs + chunked fp16 copies) ----------------
__global__ void __launch_bounds__(256) k_corr(
        const float* __restrict__ f1, const float* __restrict__ f2,
        float* __restrict__ out,
        const float* __restrict__ invn1, const float* __restrict__ invn2,
        __half* __restrict__ xin) {
    __shared__ float A_s[16][132];
    __shared__ float B_s[16][132];
    int b = blockIdx.x, q = blockIdx.y;
    int kb = (q >> 1) * 128, pb = (q & 1) * 128;
    int t = threadIdx.x, tx = t & 15, ty = t >> 4;
    const float* f1b = f1 + (size_t)b * 65536;
    const float* f2b = f2 + (size_t)b * 65536;
    float acc[8][8];
    #pragma unroll
    for (int i = 0; i < 8; ++i)
        #pragma unroll
        for (int j = 0; j < 8; ++j) acc[i][j] = 0.f;
    for (int cc = 0; cc < 16; ++cc) {
        #pragma unroll
        for (int u = 0; u < 8; ++u) {
            int e = t + 256 * u;
            int c = e >> 7, k = e & 127;
            A_s[c][k] = fmaxf(f2b[(cc * 16 + c) * HW + kb + k], 0.f);
            B_s[c][k] = fmaxf(f1b[(cc * 16 + c) * HW + pb + k], 0.f);
        }
        __syncthreads();
        #pragma unroll
        for (int c = 0; c < 16; ++c) {
            float4 a0 = *(const float4*)&A_s[c][ty * 8];
            float4 a1 = *(const float4*)&A_s[c][ty * 8 + 4];
            float4 b0 = *(const float4*)&B_s[c][tx * 8];
            float4 b1 = *(const float4*)&B_s[c][tx * 8 + 4];
            float av[8] = {a0.x, a0.y, a0.z, a0.w, a1.x, a1.y, a1.z, a1.w};
            float bv[8] = {b0.x, b0.y, b0.z, b0.w, b1.x, b1.y, b1.z, b1.w};
            #pragma unroll
            for (int i = 0; i < 8; ++i)
                #pragma unroll
                for (int j = 0; j < 8; ++j) acc[i][j] += av[i] * bv[j];
        }
        __syncthreads();
    }
    float ik[8], ip[8];
    #pragma unroll
    for (int i = 0; i < 8; ++i) ik[i] = invn2[b * HW + kb + ty * 8 + i];
    #pragma unroll
    for (int j = 0; j < 8; ++j) ip[j] = invn1[b * HW + pb + tx * 8 + j];

    float vm[8][8];
    #pragma unroll
    for (int i = 0; i < 8; ++i)
        #pragma unroll
        for (int j = 0; j < 8; ++j) vm[i][j] = acc[i][j] * ik[i] * ip[j];

    float* c1 = out + OFF_C1 + (size_t)b * 65536;
    float* c2 = out + OFF_C2 + (size_t)b * 65536;
    #pragma unroll
    for (int i = 0; i < 8; ++i) {
        int k = kb + ty * 8 + i;
        #pragma unroll
        for (int j = 0; j < 8; ++j) {
            int p = pb + tx * 8 + j;
            c1[k * HW + p] = vm[i][j];
            c2[p * HW + k] = vm[i][j];
        }
    }
    // fp16 copies into chunked layout: corr1 -> chunks 16..31, corr2 -> 48..63
    __half* xb = xin + (size_t)b * 64 * 4096;
    int ch1 = 16 + (kb >> 4) + (ty >> 1);
    int sl1 = (ty & 1) * 8;
    #pragma unroll
    for (int j = 0; j < 8; ++j) {
        int p = pb + tx * 8 + j;
        __half h[8];
        #pragma unroll
        for (int i = 0; i < 8; ++i) h[i] = __float2half_rn(vm[i][j]);
        *(uint4*)&xb[(size_t)ch1 * 4096 + p * 16 + sl1] = *(uint4*)&h[0];
    }
    int ch2 = 48 + (pb >> 4) + (tx >> 1);
    int sl2 = (tx & 1) * 8;
    #pragma unroll
    for (int i = 0; i < 8; ++i) {
        int k = kb + ty * 8 + i;
        __half h[8];
        #pragma unroll
        for (int j = 0; j < 8; ++j) h[j] = __float2half_rn(vm[i][j]);
        *(uint4*)&xb[(size_t)ch2 * 4096 + k * 16 + sl2] = *(uint4*)&h[0];
    }
}

// ---------------- input transform: V = B^T d B, per (icc, img) ----------------
__global__ void __launch_bounds__(256) k_intrans(const uint4* __restrict__ X,
                                                 uint4* __restrict__ V, int NICC) {
    __shared__ uint4 Xs4[512];        // 8KB: [256px][16ic fp16]
    __shared__ uint  SVu[8192];       // 32KB
    int icc = blockIdx.x, img = blockIdx.y, tid = threadIdx.x;
    const uint4* src = X + ((size_t)img * NICC + icc) * 512;
    Xs4[tid] = src[tid];
    Xs4[tid + 256] = src[tid + 256];
    __syncthreads();
    const uint* Xsu = (const uint*)Xs4;
    #pragma unroll
    for (int k = 0; k < 2; ++k) {
        int idx = tid + 256 * k;      // 512 half2-patches
        int icp = idx & 7, tile = idx >> 3;
        int ty = tile >> 3, tx = tile & 7;
        __half2 d[4][4];
        #pragma unroll
        for (int y = 0; y < 4; ++y) {
            int gr = 2 * ty - 1 + y;
            #pragma unroll
            for (int x = 0; x < 4; ++x) {
                int gc = 2 * tx - 1 + x;
                uint v = 0;
                if ((unsigned)gr < 16u && (unsigned)gc < 16u)
                    v = Xsu[(gr * 16 + gc) * 8 + icp];
                d[y][x] = *(__half2*)&v;
            }
        }
        __half2 tm[4][4];
        #pragma unroll
        for (int c = 0; c < 4; ++c) {
            tm[0][c] = __hsub2(d[0][c], d[2][c]);
            tm[1][c] = __hadd2(d[1][c], d[2][c]);
            tm[2][c] = __hsub2(d[2][c], d[1][c]);
            tm[3][c] = __hsub2(d[1][c], d[3][c]);
        }
        int phys = ((icp >> 2) ^ ((tile >> 2) & 1)) * 4 + (icp & 3);
        #pragma unroll
        for (int i = 0; i < 4; ++i) {
            __half2 v0 = __hsub2(tm[i][0], tm[i][2]);
            __half2 v1 = __hadd2(tm[i][1], tm[i][2]);
            __half2 v2 = __hsub2(tm[i][2], tm[i][1]);
            __half2 v3 = __hsub2(tm[i][1], tm[i][3]);
            SVu[((i * 4 + 0) * 64 + tile) * 8 + phys] = *(uint*)&v0;
            SVu[((i * 4 + 1) * 64 + tile) * 8 + phys] = *(uint*)&v1;
            SVu[((i * 4 + 2) * 64 + tile) * 8 + phys] = *(uint*)&v2;
            SVu[((i * 4 + 3) * 64 + tile) * 8 + phys] = *(uint*)&v3;
        }
    }
    __syncthreads();
    uint4* dst = V + ((size_t)img * NICC + icc) * 2048;
    const uint4* sv4 = (const uint4*)SVu;
    #pragma unroll
    for (int k = 0; k < 8; ++k) dst[tid + 256 * k] = sv4[tid + 256 * k];
}

// ---------------- Winograd GEMM: 4Mg x 2Ng x 2Tg tiling + 4-deep half-stage pipeline ----------------
// grid (OC/128, img), 512 thr = 16 warps. Half-stage = 8 t-points (ti pair), slab 48KB.
__global__ void __launch_bounds__(512, 1) k_gemm(
        const uint4* __restrict__ Vg, const uint4* __restrict__ Ug,
        const float* __restrict__ bias, __half* __restrict__ Y,
        int OC, int NICC) {
    extern __shared__ __align__(16) char sraw[];
    uint32_t sb = smem_u32(sraw);
    int img = blockIdx.y, ocb = blockIdx.x;
    int t = threadIdx.x, lane = t & 31, wid = t >> 5;
    int g = lane >> 2, tid4 = lane & 3;
    int wm = (wid & 3) * 32;
    int wn = ((wid >> 2) & 1) * 32;
    int tg = wid >> 3;                 // 0: tj in {0,1}; 1: tj in {2,3}

    const char* ug = (const char*)(Ug + (size_t)ocb * NICC * 4096);
    const char* vg = (const char*)(Vg + (size_t)img * NICC * 2048);

    uint32_t MB = sb + MBOFF;          // 4 mbarriers, +8*q
    if (t == 0) {
        MBAR_INIT(MB, 1); MBAR_INIT(MB + 8, 1);
        MBAR_INIT(MB + 16, 1); MBAR_INIT(MB + 24, 1);
    }
    __syncthreads();
    if (t == 0) {
        #pragma unroll
        for (int hs = 0; hs < 4; ++hs) {       // icc 0..1, halves 0..1
            int icc = hs >> 1, h = hs & 1;
            uint32_t fb = MB + hs * 8;
            MBAR_EXPECT_TX(fb, SLAB);
            BULK_G2S(sb + hs * SLAB,      ug + (size_t)icc * 65536 + h * UH, UH, fb);
            BULK_G2S(sb + hs * SLAB + UH, vg + (size_t)icc * 32768 + h * VH, VH, fb);
        }
    }

    // A-frag lane addressing
    int r8 = lane & 7;
    int arow = wm + r8 + ((lane & 8) ? 8 : 0);
    uint32_t khA = (lane >> 4) & 1;
    uint32_t asw = (arow >> 2) & 1;
    uint32_t aoff0 = (uint32_t)arow * 32 + ((khA ^ asw) * 16);
    uint32_t aoff1 = (uint32_t)(arow + 16) * 32 + ((khA ^ asw) * 16);
    // B-frag (two LDSM4: tiles wn..wn+15 and wn+16..wn+31)
    uint32_t q1 = (lane >> 3) & 1;
    int q2 = (lane >> 4) & 1;
    int btile = wn + q2 * 8 + r8;
    uint32_t boffA = (uint32_t)btile * 32 + ((q1 ^ ((btile >> 2) & 1)) * 16);
    int btile2 = btile + 16;
    uint32_t boffB = (uint32_t)btile2 * 32 + ((q1 ^ ((btile2 >> 2) & 1)) * 16);

    uint32_t Sv[2][4][2][2][2];        // [mi][nj][oy][tjl][rg]
    #pragma unroll
    for (int mi = 0; mi < 2; ++mi)
        #pragma unroll
        for (int nj = 0; nj < 4; ++nj)
            #pragma unroll
            for (int oy = 0; oy < 2; ++oy)
                #pragma unroll
                for (int tjl = 0; tjl < 2; ++tjl) { Sv[mi][nj][oy][tjl][0] = 0u; Sv[mi][nj][oy][tjl][1] = 0u; }
    uint32_t zz = 0u;

    int tbase = tg * 2;
    int NHS = 2 * NICC;
    for (int hs = 0; hs < NHS; ++hs) {
        int p = hs & 3, ph = (hs >> 2) & 1;
        int half = hs & 1;
        MBAR_WAIT(MB + p * 8, ph);
        uint32_t Ub = sb + p * SLAB;
        uint32_t Vb = Ub + UH;

        #pragma unroll
        for (int til = 0; til < 2; ++til) {
            const int ti = half * 2 + til;
            #pragma unroll
            for (int tjl = 0; tjl < 2; ++tjl) {
                const int tloc = til * 4 + tbase + tjl;   // t index within half-slab (0..7)
                uint32_t a0[4], a1[4], bb[8];
                LDSM4(a0[0], a0[1], a0[2], a0[3], Ub + tloc * 4096 + aoff0);
                LDSM4(a1[0], a1[1], a1[2], a1[3], Ub + tloc * 4096 + aoff1);
                LDSM4(bb[0], bb[1], bb[2], bb[3], Vb + tloc * 2048 + boffA);
                LDSM4(bb[4], bb[5], bb[6], bb[7], Vb + tloc * 2048 + boffB);
                if (ti == 0 || ti == 3) {
                    const int oy = (ti == 0) ? 0 : 1;
                    #pragma unroll
                    for (int nj = 0; nj < 4; ++nj) {
                        mma16816h(Sv[0][nj][oy][tjl], a0, bb[nj * 2], bb[nj * 2 + 1]);
                        mma16816h(Sv[1][nj][oy][tjl], a1, bb[nj * 2], bb[nj * 2 + 1]);
                    }
                } else {
                    #pragma unroll
                    for (int mi = 0; mi < 2; ++mi)
                        #pragma unroll
                        for (int nj = 0; nj < 4; ++nj) {
                            uint32_t m[2];
                            mma16816h_z(m, mi ? a1 : a0, bb[nj * 2], bb[nj * 2 + 1], zz, zz);
                            __half2 v0 = *(__half2*)&m[0];
                            __half2 v1 = *(__half2*)&m[1];
                            __half2* s0 = (__half2*)&Sv[mi][nj][0][tjl][0];
                            __half2* s1 = (__half2*)&Sv[mi][nj][1][tjl][0];
                            s0[0] = __hadd2(s0[0], v0);
                            s0[1] = __hadd2(s0[1], v1);
                            if (ti == 1) {
                                s1[0] = __hadd2(s1[0], v0);
                                s1[1] = __hadd2(s1[1], v1);
                            } else {
                                s1[0] = __hsub2(s1[0], v0);
                                s1[1] = __hsub2(s1[1], v1);
                            }
                        }
                }
            }
        }

        __syncthreads();                     // all warps done with slab p
        if (t == 0 && hs + 4 < NHS) {
            int hs2 = hs + 4;
            int icc2 = hs2 >> 1, h2 = hs2 & 1;
            uint32_t fb = MB + p * 8;
            MBAR_EXPECT_TX(fb, SLAB);
            BULK_G2S(Ub,      ug + (size_t)icc2 * 65536 + h2 * UH, UH, fb);
            BULK_G2S(Ub + UH, vg + (size_t)icc2 * 32768 + h2 * VH, VH, fb);
        }
    }

    // epilogue: two-pass tj fold across Tg pairs, via smem transpose buffer
    __half* Sh = (__half*)sraw;     // [256 px][136 oc]
    if (tg == 0) {
        // partial: P_ox0 = s_tj0 + s_tj1, P_ox1 = s_tj1 (no bias yet)
        #pragma unroll
        for (int mi = 0; mi < 2; ++mi)
            #pragma unroll
            for (int rg = 0; rg < 2; ++rg) {
                int ocl = wm + mi * 16 + g + rg * 8;
                #pragma unroll
                for (int nj = 0; nj < 4; ++nj) {
                    int T0 = wn + nj * 8 + 2 * tid4;
                    int ty0 = T0 >> 3, tx0 = T0 & 7;
                    int tx1 = (T0 + 1) & 7;
                    #pragma unroll
                    for (int oy = 0; oy < 2; ++oy) {
                        __half2 s0 = *(__half2*)&Sv[mi][nj][oy][0][rg];
                        __half2 s1 = *(__half2*)&Sv[mi][nj][oy][1][rg];
                        __half2 P0 = __hadd2(s0, s1);
                        int row = (2 * ty0 + oy) * 16;
                        Sh[(row + 2 * tx0)     * 136 + ocl] = __low2half(P0);
                        Sh[(row + 2 * tx0 + 1) * 136 + ocl] = __low2half(s1);
                        Sh[(row + 2 * tx1)     * 136 + ocl] = __high2half(P0);
                        Sh[(row + 2 * tx1 + 1) * 136 + ocl] = __high2half(s1);
                    }
                }
            }
    }
    __syncthreads();
    if (tg == 1) {
        // final: Y_ox0 = P_ox0 + s_tj2 ; Y_ox1 = P_ox1 - s_tj2 - s_tj3 ; +bias, relu
        #pragma unroll
        for (int mi = 0; mi < 2; ++mi)
            #pragma unroll
            for (int rg = 0; rg < 2; ++rg) {
                int ocl = wm + mi * 16 + g + rg * 8;
                float bz = bias[ocb * 128 + ocl];
                #pragma unroll
                for (int nj = 0; nj < 4; ++nj) {
                    int T0 = wn + nj * 8 + 2 * tid4;
                    int ty0 = T0 >> 3, tx0 = T0 & 7;
                    int tx1 = (T0 + 1) & 7;
                    #pragma unroll
                    for (int oy = 0; oy < 2; ++oy) {
                        __half2 s2 = *(__half2*)&Sv[mi][nj][oy][0][rg];
                        __half2 s3 = *(__half2*)&Sv[mi][nj][oy][1][rg];
                        __half2 Q1 = __hadd2(s2, s3);   // to subtract
                        int row = (2 * ty0 + oy) * 16;
                        int i00 = (row + 2 * tx0) * 136 + ocl;
                        int i01 = (row + 2 * tx0 + 1) * 136 + ocl;
                        int i10 = (row + 2 * tx1) * 136 + ocl;
                        int i11 = (row + 2 * tx1 + 1) * 136 + ocl;
                        float v00 = __half2float(Sh[i00]) + __low2float(s2)  + bz;
                        float v01 = __half2float(Sh[i01]) - __low2float(Q1)  + bz;
                        float v10 = __half2float(Sh[i10]) + __high2float(s2) + bz;
                        float v11 = __half2float(Sh[i11]) - __high2float(Q1) + bz;
                        Sh[i00] = __float2half_rn(fmaxf(v00, 0.f));
                        Sh[i01] = __float2half_rn(fmaxf(v01, 0.f));
                        Sh[i10] = __float2half_rn(fmaxf(v10, 0.f));
                        Sh[i11] = __float2half_rn(fmaxf(v11, 0.f));
                    }
                }
            }
    }
    __syncthreads();
    __half* Yb = Y + ((size_t)img * (OC >> 4) + ocb * 8) * 4096;
    #pragma unroll
    for (int k2 = 0; k2 < 8; ++k2) {
        int idx = t + 512 * k2;               // 4096 = 8 chunks * 256 px * 2 halves
        int c8 = idx >> 9, rem = idx & 511, px = rem >> 1, hf = rem & 1;
        uint4 v = *(uint4*)&Sh[px * 136 + c8 * 16 + hf * 8];
        *(uint4*)&Yb[((size_t)c8 * 256 + px) * 16 + hf * 8] = v;
    }
}

// ---------------- final head: 1x1 (diag) + avgpool + softmax ----------------
__global__ void k_final(const __half* __restrict__ Y2,
                        const float* __restrict__ wT,
                        float* __restrict__ out) {
    int b = blockIdx.x, p = threadIdx.x;
    const __half* yb = Y2 + (size_t)b * 32 * 4096;
    float a0 = 0.f, a1 = 0.f;
    for (int c = 0; c < 32; ++c) {
        __half h[16];
        *(uint4*)&h[0] = *(const uint4*)&yb[((size_t)c * 256 + p) * 16];
        *(uint4*)&h[8] = *(const uint4*)&yb[((size_t)c * 256 + p) * 16 + 8];
        const float* wr = wT + (size_t)c * 16 * 512 + p;
        #pragma unroll
        for (int i = 0; i < 16; ++i) {
            float y = __half2float(h[i]);
            a0 += wr[i * 512] * y;
            a1 += wr[i * 512 + 256] * y;
        }
    }
    a0 = fmaxf(a0, 0.f);
    a1 = fmaxf(a1, 0.f);
    __shared__ float s0[256], s1[256];
    s0[p] = a0; s1[p] = a1;
    __syncthreads();
    for (int st = 128; st > 0; st >>= 1) {
        if (p < st) { s0[p] += s0[p + st]; s1[p] += s1[p + st]; }
        __syncthreads();
    }
    if (p == 0) {
        float m0 = s0[0] * (1.0f / 256.0f);
        float m1 = s1[0] * (1.0f / 256.0f);
        float mx = fmaxf(m0, m1);
        float e0 = expf(m0 - mx), e1 = expf(m1 - mx);
        float inv = 1.0f / (e0 + e1);
        out[b * 2 + 0] = e0 * inv;
        out[b * 2 + 1] = e1 * inv;
    }
}

// ---------------- launch ----------------
extern "C" void kernel_launch(void* const* d_in, const int* in_sizes, int n_in,
                              void* d_out, int out_size) {
    const float* f1      = (const float*)d_in[0];
    const float* f2      = (const float*)d_in[1];
    const float* conv1_w = (const float*)d_in[2];
    const float* conv1_b = (const float*)d_in[3];
    const float* conv2_w = (const float*)d_in[4];
    const float* conv2_b = (const float*)d_in[5];
    const float* cls_w   = (const float*)d_in[6];
    float* out = (float*)d_out;

    uint4 *x1, *y1, *y2, *vv, *u1, *u2;
    float *invn1, *invn2, *wclsT;
    cudaGetSymbolAddress((void**)&x1,    g_X1);
    cudaGetSymbolAddress((void**)&y1,    g_Y1);
    cudaGetSymbolAddress((void**)&y2,    g_Y2);
    cudaGetSymbolAddress((void**)&vv,    g_V);
    cudaGetSymbolAddress((void**)&u1,    g_U1);
    cudaGetSymbolAddress((void**)&u2,    g_U2);
    cudaGetSymbolAddress((void**)&invn1, g_invn1);
    cudaGetSymbolAddress((void**)&invn2, g_invn2);
    cudaGetSymbolAddress((void**)&wclsT, g_wclsT);

    cudaFuncSetAttribute(k_gemm,   cudaFuncAttributeMaxDynamicSharedMemorySize, SMEMG);
    cudaFuncSetAttribute(k_wtrans, cudaFuncAttributeMaxDynamicSharedMemorySize, 65536);

    k_norm<<<NB, 256>>>(f1, f2, (__half*)x1, invn1, invn2);
    k_wtrans<<<dim3(8, 64), 256, 65536>>>(conv1_w, u1, 64);
    k_wtrans<<<dim3(4, 64), 256, 65536>>>(conv2_w, u2, 64);
    k_prepcls<<<(512 * 512 + 255) / 256, 256>>>(cls_w, wclsT);

    k_corr<<<dim3(NB, 4), 256>>>(f1, f2, out, invn1, invn2, (__half*)x1);

    k_intrans<<<dim3(64, NB), 256>>>(x1, vv, 64);
    k_gemm<<<dim3(8, NB), 512, SMEMG>>>(vv, u1, conv1_b, (__half*)y1, 1024, 64);
    k_intrans<<<dim3(64, NB), 256>>>(y1, vv, 64);
    k_gemm<<<dim3(4, NB), 512, SMEMG>>>(vv, u2, conv2_b, (__half*)y2, 512, 64);

    k_final<<<NB, 256>>>((__half*)y2, wclsT, out);
}

// round 16
// speedup vs baseline: 3.7643x; 3.7643x over previous
#include <cuda_runtime.h>
#include <cuda_fp16.h>
#include <cstdint>

#define NB 256
#define HW 256
#define OFF_C1 512
#define OFF_C2 (512 + 16777216)

// half-stage slabs: U half 32KB + V half 16KB = 48KB; 4 buffers = 192KB
#define UH     32768
#define VH     16384
#define SLAB   49152
#define MBOFF  196608
#define SMEMG  196672

// ---------------- device scratch ----------------
__device__ uint4 g_X1[(size_t)NB * 64 * 512];    // [img][64 ch-chunk][256px][16] fp16
__device__ uint4 g_Y1[(size_t)NB * 64 * 512];
__device__ uint4 g_Y2[(size_t)NB * 32 * 512];
__device__ uint4 g_V [(size_t)NB * 64 * 2048];   // [img][icc][16t][64tile][32B]
__device__ uint4 g_U1[8 * 64 * 4096];            // [ocb][icc][16t][128oc][32B]
__device__ uint4 g_U2[4 * 64 * 4096];
__device__ float g_invn1[NB * HW];
__device__ float g_invn2[NB * HW];
__device__ float g_wclsT[512 * 512];

// ---------------- PTX helpers ----------------
__device__ __forceinline__ uint32_t smem_u32(const void* p) {
    uint32_t a;
    asm("{ .reg .u64 t; cvta.to.shared.u64 t, %1; cvt.u32.u64 %0, t; }" : "=r"(a) : "l"(p));
    return a;
}
#define MBAR_INIT(a, c)  asm volatile("mbarrier.init.shared.b64 [%0], %1;" :: "r"(a), "r"((uint32_t)(c)) : "memory")
#define MBAR_EXPECT_TX(a, n) \
    asm volatile("mbarrier.arrive.expect_tx.shared.b64 _, [%0], %1;" :: "r"(a), "r"((uint32_t)(n)) : "memory")
#define MBAR_WAIT(a, par) do {                                                    \
    uint32_t _m = (a), _p = (par), _d;                                            \
    asm volatile("{\n\t.reg .pred p;\n\t"                                         \
        "mbarrier.try_wait.parity.acquire.cta.shared::cta.b64 p, [%1], %2;\n\t"   \
        "selp.b32 %0,1,0,p;\n\t}" : "=r"(_d) : "r"(_m), "r"(_p) : "memory");      \
    if (!_d) {                                                                    \
        asm volatile("{\n\t.reg .pred P1;\n\tWL_%=:\n\t"                          \
            "mbarrier.try_wait.parity.acquire.cta.shared::cta.b64 P1, [%0], %1, 0x989680;\n\t" \
            "@P1 bra.uni WD_%=;\n\tbra.uni WL_%=;\n\tWD_%=:\n\t}"                 \
            :: "r"(_m), "r"(_p) : "memory");                                      \
    }                                                                             \
} while (0)
#define BULK_G2S(dst, src, bytes, bar) \
    asm volatile("cp.async.bulk.shared::cta.global.mbarrier::complete_tx::bytes [%0], [%1], %2, [%3];" \
        :: "r"(dst), "l"(src), "r"((uint32_t)(bytes)), "r"(bar) : "memory")
#define LDSM4(r0, r1, r2, r3, a) \
    asm volatile("ldmatrix.sync.aligned.m8n8.x4.shared.b16 {%0,%1,%2,%3}, [%4];" \
        : "=r"(r0), "=r"(r1), "=r"(r2), "=r"(r3) : "r"(a))
// in-place f16 HMMA: D = C = c (accumulate)
__device__ __forceinline__ void mma16816h(uint32_t* c, const uint32_t* a, uint32_t b0, uint32_t b1) {
    asm volatile(
        "mma.sync.aligned.m16n8k16.row.col.f16.f16.f16.f16 "
        "{%0,%1}, {%2,%3,%4,%5}, {%6,%7}, {%0,%1};\n"
        : "+r"(c[0]), "+r"(c[1])
        : "r"(a[0]), "r"(a[1]), "r"(a[2]), "r"(a[3]), "r"(b0), "r"(b1));
}
// D != C form (C = persistent zero regs)
__device__ __forceinline__ void mma16816h_z(uint32_t* d, const uint32_t* a, uint32_t b0, uint32_t b1,
                                            uint32_t z0, uint32_t z1) {
    asm volatile(
        "mma.sync.aligned.m16n8k16.row.col.f16.f16.f16.f16 "
        "{%0,%1}, {%2,%3,%4,%5}, {%6,%7}, {%8,%9};\n"
        : "=r"(d[0]), "=r"(d[1])
        : "r"(a[0]), "r"(a[1]), "r"(a[2]), "r"(a[3]), "r"(b0), "r"(b1), "r"(z0), "r"(z1));
}

// ---------------- K0: relu + channel norms + chunked fp16 layout ----------------
__global__ void k_norm(const float* __restrict__ f1, const float* __restrict__ f2,
                       __half* __restrict__ xin,
                       float* __restrict__ invn1, float* __restrict__ invn2) {
    int b = blockIdx.x, p = threadIdx.x;
    const float* f1b = f1 + (size_t)b * 65536;
    const float* f2b = f2 + (size_t)b * 65536;
    __half* xb = xin + (size_t)b * 64 * 4096;
    float s1 = 0.f, s2 = 0.f;
    for (int ch = 0; ch < 16; ++ch) {
        __half h1[16], h2[16];
        #pragma unroll
        for (int i = 0; i < 16; ++i) {
            float v1 = fmaxf(f1b[(ch * 16 + i) * HW + p], 0.f);
            float v2 = fmaxf(f2b[(ch * 16 + i) * HW + p], 0.f);
            s1 += v1 * v1;  s2 += v2 * v2;
            h1[i] = __float2half_rn(v1);
            h2[i] = __float2half_rn(v2);
        }
        *(uint4*)&xb[(size_t)ch * 4096 + p * 16]            = *(uint4*)&h1[0];
        *(uint4*)&xb[(size_t)ch * 4096 + p * 16 + 8]        = *(uint4*)&h1[8];
        *(uint4*)&xb[(size_t)(32 + ch) * 4096 + p * 16]     = *(uint4*)&h2[0];
        *(uint4*)&xb[(size_t)(32 + ch) * 4096 + p * 16 + 8] = *(uint4*)&h2[8];
    }
    invn1[b * HW + p] = 1.0f / fmaxf(sqrtf(s1), 1e-12f);
    invn2[b * HW + p] = 1.0f / fmaxf(sqrtf(s2), 1e-12f);
}

// ---------------- weight transform: U = G g G^T (ti=3 rows NEGATED) ----------------
__global__ void k_wtrans(const float* __restrict__ w, uint4* __restrict__ U,
                         int NICC) {
    extern __shared__ __align__(16) char su[];
    int ocb = blockIdx.x, icc = blockIdx.y, tid = threadIdx.x;
    #pragma unroll 1
    for (int k = 0; k < 8; ++k) {
        int pr = tid + 256 * k;               // 2048 (oc,ic) pairs
        int oc_l = pr >> 4, ic_l = pr & 15;
        int oc = ocb * 128 + oc_l;
        int ic = icc * 16 + ic_l;
        const float* gw = w + ((size_t)oc * 1024 + ic) * 9;
        float g00 = gw[0], g01 = gw[1], g02 = gw[2];
        float g10 = gw[3], g11 = gw[4], g12 = gw[5];
        float g20 = gw[6], g21 = gw[7], g22 = gw[8];
        float t0[3] = {g00, g01, g02};
        float t1[3] = {0.5f*(g00+g10+g20), 0.5f*(g01+g11+g21), 0.5f*(g02+g12+g22)};
        float t2[3] = {0.5f*(g00-g10+g20), 0.5f*(g01-g11+g21), 0.5f*(g02-g12+g22)};
        float t3[3] = {g20, g21, g22};
        float* tr[4] = {t0, t1, t2, t3};
        int sw = (oc_l >> 2) & 1;
        int phys = ((ic_l >> 3) ^ sw) * 16 + (ic_l & 7) * 2;
        #pragma unroll
        for (int i = 0; i < 4; ++i) {
            float* ti = tr[i];
            float sgn = (i == 3) ? -1.f : 1.f;     // bake A^T oy1 sign for ti=3
            float u0 = ti[0];
            float u1 = 0.5f * (ti[0] + ti[1] + ti[2]);
            float u2 = 0.5f * (ti[0] - ti[1] + ti[2]);
            float u3 = ti[2];
            float uv[4] = {u0, u1, u2, u3};
            #pragma unroll
            for (int j = 0; j < 4; ++j) {
                int t = i * 4 + j;
                *(__half*)(su + (t * 128 + oc_l) * 32 + phys) = __float2half_rn(sgn * uv[j]);
            }
        }
    }
    __syncthreads();
    uint4* dst = U + ((size_t)(ocb * NICC + icc)) * 4096;
    const uint4* s4 = (const uint4*)su;
    #pragma unroll 1
    for (int k = 0; k < 16; ++k) dst[tid + 256 * k] = s4[tid + 256 * k];
}

__global__ void k_prepcls(const float* __restrict__ w, float* __restrict__ o) {
    int idx = blockIdx.x * blockDim.x + threadIdx.x;
    if (idx >= 512 * 512) return;
    int ic = idx >> 9, oc = idx & 511;
    o[idx] = w[oc * 512 + ic];
}

// ---------------- K1: correlation GEMM (fp32 outputs + chunked fp16 copies) ----------------
__global__ void __launch_bounds__(256) k_corr(
        const float* __restrict__ f1, const float* __restrict__ f2,
        float* __restrict__ out,
        const float* __restrict__ invn1, const float* __restrict__ invn2,
        __half* __restrict__ xin) {
    __shared__ float A_s[16][132];
    __shared__ float B_s[16][132];
    int b = blockIdx.x, q = blockIdx.y;
    int kb = (q >> 1) * 128, pb = (q & 1) * 128;
    int t = threadIdx.x, tx = t & 15, ty = t >> 4;
    const float* f1b = f1 + (size_t)b * 65536;
    const float* f2b = f2 + (size_t)b * 65536;
    float acc[8][8];
    #pragma unroll
    for (int i = 0; i < 8; ++i)
        #pragma unroll
        for (int j = 0; j < 8; ++j) acc[i][j] = 0.f;
    for (int cc = 0; cc < 16; ++cc) {
        #pragma unroll
        for (int u = 0; u < 8; ++u) {
            int e = t + 256 * u;
            int c = e >> 7, k = e & 127;
            A_s[c][k] = fmaxf(f2b[(cc * 16 + c) * HW + kb + k], 0.f);
            B_s[c][k] = fmaxf(f1b[(cc * 16 + c) * HW + pb + k], 0.f);
        }
        __syncthreads();
        #pragma unroll
        for (int c = 0; c < 16; ++c) {
            float4 a0 = *(const float4*)&A_s[c][ty * 8];
            float4 a1 = *(const float4*)&A_s[c][ty * 8 + 4];
            float4 b0 = *(const float4*)&B_s[c][tx * 8];
            float4 b1 = *(const float4*)&B_s[c][tx * 8 + 4];
            float av[8] = {a0.x, a0.y, a0.z, a0.w, a1.x, a1.y, a1.z, a1.w};
            float bv[8] = {b0.x, b0.y, b0.z, b0.w, b1.x, b1.y, b1.z, b1.w};
            #pragma unroll
            for (int i = 0; i < 8; ++i)
                #pragma unroll
                for (int j = 0; j < 8; ++j) acc[i][j] += av[i] * bv[j];
        }
        __syncthreads();
    }
    float ik[8], ip[8];
    #pragma unroll
    for (int i = 0; i < 8; ++i) ik[i] = invn2[b * HW + kb + ty * 8 + i];
    #pragma unroll
    for (int j = 0; j < 8; ++j) ip[j] = invn1[b * HW + pb + tx * 8 + j];

    float vm[8][8];
    #pragma unroll
    for (int i = 0; i < 8; ++i)
        #pragma unroll
        for (int j = 0; j < 8; ++j) vm[i][j] = acc[i][j] * ik[i] * ip[j];

    float* c1 = out + OFF_C1 + (size_t)b * 65536;
    float* c2 = out + OFF_C2 + (size_t)b * 65536;
    #pragma unroll
    for (int i = 0; i < 8; ++i) {
        int k = kb + ty * 8 + i;
        #pragma unroll
        for (int j = 0; j < 8; ++j) {
            int p = pb + tx * 8 + j;
            c1[k * HW + p] = vm[i][j];
            c2[p * HW + k] = vm[i][j];
        }
    }
    // fp16 copies into chunked layout: corr1 -> chunks 16..31, corr2 -> 48..63
    __half* xb = xin + (size_t)b * 64 * 4096;
    int ch1 = 16 + (kb >> 4) + (ty >> 1);
    int sl1 = (ty & 1) * 8;
    #pragma unroll
    for (int j = 0; j < 8; ++j) {
        int p = pb + tx * 8 + j;
        __half h[8];
        #pragma unroll
        for (int i = 0; i < 8; ++i) h[i] = __float2half_rn(vm[i][j]);
        *(uint4*)&xb[(size_t)ch1 * 4096 + p * 16 + sl1] = *(uint4*)&h[0];
    }
    int ch2 = 48 + (pb >> 4) + (tx >> 1);
    int sl2 = (tx & 1) * 8;
    #pragma unroll
    for (int i = 0; i < 8; ++i) {
        int k = kb + ty * 8 + i;
        __half h[8];
        #pragma unroll
        for (int j = 0; j < 8; ++j) h[j] = __float2half_rn(vm[i][j]);
        *(uint4*)&xb[(size_t)ch2 * 4096 + k * 16 + sl2] = *(uint4*)&h[0];
    }
}

// ---------------- input transform: V = B^T d B, per (icc, img) ----------------
__global__ void __launch_bounds__(256) k_intrans(const uint4* __restrict__ X,
                                                 uint4* __restrict__ V, int NICC) {
    __shared__ uint4 Xs4[512];        // 8KB: [256px][16ic fp16]
    __shared__ uint  SVu[8192];       // 32KB
    int icc = blockIdx.x, img = blockIdx.y, tid = threadIdx.x;
    const uint4* src = X + ((size_t)img * NICC + icc) * 512;
    Xs4[tid] = src[tid];
    Xs4[tid + 256] = src[tid + 256];
    __syncthreads();
    const uint* Xsu = (const uint*)Xs4;
    #pragma unroll
    for (int k = 0; k < 2; ++k) {
        int idx = tid + 256 * k;      // 512 half2-patches
        int icp = idx & 7, tile = idx >> 3;
        int ty = tile >> 3, tx = tile & 7;
        __half2 d[4][4];
        #pragma unroll
        for (int y = 0; y < 4; ++y) {
            int gr = 2 * ty - 1 + y;
            #pragma unroll
            for (int x = 0; x < 4; ++x) {
                int gc = 2 * tx - 1 + x;
                uint v = 0;
                if ((unsigned)gr < 16u && (unsigned)gc < 16u)
                    v = Xsu[(gr * 16 + gc) * 8 + icp];
                d[y][x] = *(__half2*)&v;
            }
        }
        __half2 tm[4][4];
        #pragma unroll
        for (int c = 0; c < 4; ++c) {
            tm[0][c] = __hsub2(d[0][c], d[2][c]);
            tm[1][c] = __hadd2(d[1][c], d[2][c]);
            tm[2][c] = __hsub2(d[2][c], d[1][c]);
            tm[3][c] = __hsub2(d[1][c], d[3][c]);
        }
        int phys = ((icp >> 2) ^ ((tile >> 2) & 1)) * 4 + (icp & 3);
        #pragma unroll
        for (int i = 0; i < 4; ++i) {
            __half2 v0 = __hsub2(tm[i][0], tm[i][2]);
            __half2 v1 = __hadd2(tm[i][1], tm[i][2]);
            __half2 v2 = __hsub2(tm[i][2], tm[i][1]);
            __half2 v3 = __hsub2(tm[i][1], tm[i][3]);
            SVu[((i * 4 + 0) * 64 + tile) * 8 + phys] = *(uint*)&v0;
            SVu[((i * 4 + 1) * 64 + tile) * 8 + phys] = *(uint*)&v1;
            SVu[((i * 4 + 2) * 64 + tile) * 8 + phys] = *(uint*)&v2;
            SVu[((i * 4 + 3) * 64 + tile) * 8 + phys] = *(uint*)&v3;
        }
    }
    __syncthreads();
    uint4* dst = V + ((size_t)img * NICC + icc) * 2048;
    const uint4* sv4 = (const uint4*)SVu;
    #pragma unroll
    for (int k = 0; k < 8; ++k) dst[tid + 256 * k] = sv4[tid + 256 * k];
}

// ---------------- Winograd GEMM: 4Mg x 2Ng x 2Tg tiling + 4-deep half-stage pipeline ----------------
// grid (OC/128, img), 512 thr = 16 warps. Half-stage = 8 t-points (COMPILE-TIME ti pair).
__global__ void __launch_bounds__(512, 1) k_gemm(
        const uint4* __restrict__ Vg, const uint4* __restrict__ Ug,
        const float* __restrict__ bias, __half* __restrict__ Y,
        int OC, int NICC) {
    extern __shared__ __align__(16) char sraw[];
    uint32_t sb = smem_u32(sraw);
    int img = blockIdx.y, ocb = blockIdx.x;
    int t = threadIdx.x, lane = t & 31, wid = t >> 5;
    int g = lane >> 2, tid4 = lane & 3;
    int wm = (wid & 3) * 32;
    int wn = ((wid >> 2) & 1) * 32;
    int tg = wid >> 3;                 // 0: tj in {0,1}; 1: tj in {2,3}

    const char* ug = (const char*)(Ug + (size_t)ocb * NICC * 4096);
    const char* vg = (const char*)(Vg + (size_t)img * NICC * 2048);

    uint32_t MB = sb + MBOFF;          // 4 mbarriers, +8*q
    if (t == 0) {
        MBAR_INIT(MB, 1); MBAR_INIT(MB + 8, 1);
        MBAR_INIT(MB + 16, 1); MBAR_INIT(MB + 24, 1);
    }
    __syncthreads();
    if (t == 0) {
        #pragma unroll
        for (int hs = 0; hs < 4; ++hs) {       // icc 0..1, halves 0..1
            int icc = hs >> 1, h = hs & 1;
            uint32_t fb = MB + hs * 8;
            MBAR_EXPECT_TX(fb, SLAB);
            BULK_G2S(sb + hs * SLAB,      ug + (size_t)icc * 65536 + h * UH, UH, fb);
            BULK_G2S(sb + hs * SLAB + UH, vg + (size_t)icc * 32768 + h * VH, VH, fb);
        }
    }

    // A-frag lane addressing
    int r8 = lane & 7;
    int arow = wm + r8 + ((lane & 8) ? 8 : 0);
    uint32_t khA = (lane >> 4) & 1;
    uint32_t asw = (arow >> 2) & 1;
    uint32_t aoff0 = (uint32_t)arow * 32 + ((khA ^ asw) * 16);
    uint32_t aoff1 = (uint32_t)(arow + 16) * 32 + ((khA ^ asw) * 16);
    // B-frag (two LDSM4: tiles wn..wn+15 and wn+16..wn+31)
    uint32_t q1 = (lane >> 3) & 1;
    int q2 = (lane >> 4) & 1;
    int btile = wn + q2 * 8 + r8;
    uint32_t boffA = (uint32_t)btile * 32 + ((q1 ^ ((btile >> 2) & 1)) * 16);
    int btile2 = btile + 16;
    uint32_t boffB = (uint32_t)btile2 * 32 + ((q1 ^ ((btile2 >> 2) & 1)) * 16);

    uint32_t Sv[2][4][2][2][2];        // [mi][nj][oy][tjl][rg]
    #pragma unroll
    for (int mi = 0; mi < 2; ++mi)
        #pragma unroll
        for (int nj = 0; nj < 4; ++nj)
            #pragma unroll
            for (int oy = 0; oy < 2; ++oy)
                #pragma unroll
                for (int tjl = 0; tjl < 2; ++tjl) { Sv[mi][nj][oy][tjl][0] = 0u; Sv[mi][nj][oy][tjl][1] = 0u; }
    uint32_t zz = 0u;

    int tbase = tg * 2;
    int NHS = 2 * NICC;
    for (int icc = 0; icc < NICC; ++icc) {
        #pragma unroll
        for (int half = 0; half < 2; ++half) {       // COMPILE-TIME half -> static ti/oy
            int hs = 2 * icc + half;
            int p = hs & 3, ph = (hs >> 2) & 1;
            MBAR_WAIT(MB + p * 8, ph);
            uint32_t Ub = sb + p * SLAB;
            uint32_t Vb = Ub + UH;

            #pragma unroll
            for (int til = 0; til < 2; ++til) {
                const int ti = half * 2 + til;       // constant: 0..3
                #pragma unroll
                for (int tjl = 0; tjl < 2; ++tjl) {
                    const int tloc = til * 4 + tbase + tjl;   // t within half-slab (0..7)
                    uint32_t a0[4], a1[4], bb[8];
                    LDSM4(a0[0], a0[1], a0[2], a0[3], Ub + tloc * 4096 + aoff0);
                    LDSM4(a1[0], a1[1], a1[2], a1[3], Ub + tloc * 4096 + aoff1);
                    LDSM4(bb[0], bb[1], bb[2], bb[3], Vb + tloc * 2048 + boffA);
                    LDSM4(bb[4], bb[5], bb[6], bb[7], Vb + tloc * 2048 + boffB);
                    if (ti == 0 || ti == 3) {
                        const int oy = (ti == 0) ? 0 : 1;
                        #pragma unroll
                        for (int nj = 0; nj < 4; ++nj) {
                            mma16816h(Sv[0][nj][oy][tjl], a0, bb[nj * 2], bb[nj * 2 + 1]);
                            mma16816h(Sv[1][nj][oy][tjl], a1, bb[nj * 2], bb[nj * 2 + 1]);
                        }
                    } else {
                        #pragma unroll
                        for (int mi = 0; mi < 2; ++mi)
                            #pragma unroll
                            for (int nj = 0; nj < 4; ++nj) {
                                uint32_t m[2];
                                mma16816h_z(m, mi ? a1 : a0, bb[nj * 2], bb[nj * 2 + 1], zz, zz);
                                __half2 v0 = *(__half2*)&m[0];
                                __half2 v1 = *(__half2*)&m[1];
                                __half2* s0 = (__half2*)&Sv[mi][nj][0][tjl][0];
                                __half2* s1 = (__half2*)&Sv[mi][nj][1][tjl][0];
                                s0[0] = __hadd2(s0[0], v0);
                                s0[1] = __hadd2(s0[1], v1);
                                if (ti == 1) {
                                    s1[0] = __hadd2(s1[0], v0);
                                    s1[1] = __hadd2(s1[1], v1);
                                } else {
                                    s1[0] = __hsub2(s1[0], v0);
                                    s1[1] = __hsub2(s1[1], v1);
                                }
                            }
                    }
                }
            }

            __syncthreads();                     // all warps done with slab p
            if (t == 0 && hs + 4 < NHS) {
                int hs2 = hs + 4;
                int icc2 = hs2 >> 1, h2 = hs2 & 1;
                uint32_t fb = MB + p * 8;
                MBAR_EXPECT_TX(fb, SLAB);
                BULK_G2S(Ub,      ug + (size_t)icc2 * 65536 + h2 * UH, UH, fb);
                BULK_G2S(Ub + UH, vg + (size_t)icc2 * 32768 + h2 * VH, VH, fb);
            }
        }
    }

    // epilogue: two-pass tj fold across Tg pairs, via smem transpose buffer
    __half* Sh = (__half*)sraw;     // [256 px][136 oc]
    if (tg == 0) {
        // partial: P_ox0 = s_tj0 + s_tj1, P_ox1 = s_tj1 (no bias yet)
        #pragma unroll
        for (int mi = 0; mi < 2; ++mi)
            #pragma unroll
            for (int rg = 0; rg < 2; ++rg) {
                int ocl = wm + mi * 16 + g + rg * 8;
                #pragma unroll
                for (int nj = 0; nj < 4; ++nj) {
                    int T0 = wn + nj * 8 + 2 * tid4;
                    int ty0 = T0 >> 3, tx0 = T0 & 7;
                    int tx1 = (T0 + 1) & 7;
                    #pragma unroll
                    for (int oy = 0; oy < 2; ++oy) {
                        __half2 s0 = *(__half2*)&Sv[mi][nj][oy][0][rg];
                        __half2 s1 = *(__half2*)&Sv[mi][nj][oy][1][rg];
                        __half2 P0 = __hadd2(s0, s1);
                        int row = (2 * ty0 + oy) * 16;
                        Sh[(row + 2 * tx0)     * 136 + ocl] = __low2half(P0);
                        Sh[(row + 2 * tx0 + 1) * 136 + ocl] = __low2half(s1);
                        Sh[(row + 2 * tx1)     * 136 + ocl] = __high2half(P0);
                        Sh[(row + 2 * tx1 + 1) * 136 + ocl] = __high2half(s1);
                    }
                }
            }
    }
    __syncthreads();
    if (tg == 1) {
        // final: Y_ox0 = P_ox0 + s_tj2 ; Y_ox1 = P_ox1 - s_tj2 - s_tj3 ; +bias, relu
        #pragma unroll
        for (int mi = 0; mi < 2; ++mi)
            #pragma unroll
            for (int rg = 0; rg < 2; ++rg) {
                int ocl = wm + mi * 16 + g + rg * 8;
                float bz = bias[ocb * 128 + ocl];
                #pragma unroll
                for (int nj = 0; nj < 4; ++nj) {
                    int T0 = wn + nj * 8 + 2 * tid4;
                    int ty0 = T0 >> 3, tx0 = T0 & 7;
                    int tx1 = (T0 + 1) & 7;
                    #pragma unroll
                    for (int oy = 0; oy < 2; ++oy) {
                        __half2 s2 = *(__half2*)&Sv[mi][nj][oy][0][rg];
                        __half2 s3 = *(__half2*)&Sv[mi][nj][oy][1][rg];
                        __half2 Q1 = __hadd2(s2, s3);   // to subtract
                        int row = (2 * ty0 + oy) * 16;
                        int i00 = (row + 2 * tx0) * 136 + ocl;
                        int i01 = (row + 2 * tx0 + 1) * 136 + ocl;
                        int i10 = (row + 2 * tx1) * 136 + ocl;
                        int i11 = (row + 2 * tx1 + 1) * 136 + ocl;
                        float v00 = __half2float(Sh[i00]) + __low2float(s2)  + bz;
                        float v01 = __half2float(Sh[i01]) - __low2float(Q1)  + bz;
                        float v10 = __half2float(Sh[i10]) + __high2float(s2) + bz;
                        float v11 = __half2float(Sh[i11]) - __high2float(Q1) + bz;
                        Sh[i00] = __float2half_rn(fmaxf(v00, 0.f));
                        Sh[i01] = __float2half_rn(fmaxf(v01, 0.f));
                        Sh[i10] = __float2half_rn(fmaxf(v10, 0.f));
                        Sh[i11] = __float2half_rn(fmaxf(v11, 0.f));
                    }
                }
            }
    }
    __syncthreads();
    __half* Yb = Y + ((size_t)img * (OC >> 4) + ocb * 8) * 4096;
    #pragma unroll
    for (int k2 = 0; k2 < 8; ++k2) {
        int idx = t + 512 * k2;               // 4096 = 8 chunks * 256 px * 2 halves
        int c8 = idx >> 9, rem = idx & 511, px = rem >> 1, hf = rem & 1;
        uint4 v = *(uint4*)&Sh[px * 136 + c8 * 16 + hf * 8];
        *(uint4*)&Yb[((size_t)c8 * 256 + px) * 16 + hf * 8] = v;
    }
}

// ---------------- final head: 1x1 (diag) + avgpool + softmax ----------------
__global__ void k_final(const __half* __restrict__ Y2,
                        const float* __restrict__ wT,
                        float* __restrict__ out) {
    int b = blockIdx.x, p = threadIdx.x;
    const __half* yb = Y2 + (size_t)b * 32 * 4096;
    float a0 = 0.f, a1 = 0.f;
    for (int c = 0; c < 32; ++c) {
        __half h[16];
        *(uint4*)&h[0] = *(const uint4*)&yb[((size_t)c * 256 + p) * 16];
        *(uint4*)&h[8] = *(const uint4*)&yb[((size_t)c * 256 + p) * 16 + 8];
        const float* wr = wT + (size_t)c * 16 * 512 + p;
        #pragma unroll
        for (int i = 0; i < 16; ++i) {
            float y = __half2float(h[i]);
            a0 += wr[i * 512] * y;
            a1 += wr[i * 512 + 256] * y;
        }
    }
    a0 = fmaxf(a0, 0.f);
    a1 = fmaxf(a1, 0.f);
    __shared__ float s0[256], s1[256];
    s0[p] = a0; s1[p] = a1;
    __syncthreads();
    for (int st = 128; st > 0; st >>= 1) {
        if (p < st) { s0[p] += s0[p + st]; s1[p] += s1[p + st]; }
        __syncthreads();
    }
    if (p == 0) {
        float m0 = s0[0] * (1.0f / 256.0f);
        float m1 = s1[0] * (1.0f / 256.0f);
        float mx = fmaxf(m0, m1);
        float e0 = expf(m0 - mx), e1 = expf(m1 - mx);
        float inv = 1.0f / (e0 + e1);
        out[b * 2 + 0] = e0 * inv;
        out[b * 2 + 1] = e1 * inv;
    }
}

// ---------------- launch ----------------
extern "C" void kernel_launch(void* const* d_in, const int* in_sizes, int n_in,
                              void* d_out, int out_size) {
    const float* f1      = (const float*)d_in[0];
    const float* f2      = (const float*)d_in[1];
    const float* conv1_w = (const float*)d_in[2];
    const float* conv1_b = (const float*)d_in[3];
    const float* conv2_w = (const float*)d_in[4];
    const float* conv2_b = (const float*)d_in[5];
    const float* cls_w   = (const float*)d_in[6];
    float* out = (float*)d_out;

    uint4 *x1, *y1, *y2, *vv, *u1, *u2;
    float *invn1, *invn2, *wclsT;
    cudaGetSymbolAddress((void**)&x1,    g_X1);
    cudaGetSymbolAddress((void**)&y1,    g_Y1);
    cudaGetSymbolAddress((void**)&y2,    g_Y2);
    cudaGetSymbolAddress((void**)&vv,    g_V);
    cudaGetSymbolAddress((void**)&u1,    g_U1);
    cudaGetSymbolAddress((void**)&u2,    g_U2);
    cudaGetSymbolAddress((void**)&invn1, g_invn1);
    cudaGetSymbolAddress((void**)&invn2, g_invn2);
    cudaGetSymbolAddress((void**)&wclsT, g_wclsT);

    cudaFuncSetAttribute(k_gemm,   cudaFuncAttributeMaxDynamicSharedMemorySize, SMEMG);
    cudaFuncSetAttribute(k_wtrans, cudaFuncAttributeMaxDynamicSharedMemorySize, 65536);

    k_norm<<<NB, 256>>>(f1, f2, (__half*)x1, invn1, invn2);
    k_wtrans<<<dim3(8, 64), 256, 65536>>>(conv1_w, u1, 64);
    k_wtrans<<<dim3(4, 64), 256, 65536>>>(conv2_w, u2, 64);
    k_prepcls<<<(512 * 512 + 255) / 256, 256>>>(cls_w, wclsT);

    k_corr<<<dim3(NB, 4), 256>>>(f1, f2, out, invn1, invn2, (__half*)x1);

    k_intrans<<<dim3(64, NB), 256>>>(x1, vv, 64);
    k_gemm<<<dim3(8, NB), 512, SMEMG>>>(vv, u1, conv1_b, (__half*)y1, 1024, 64);
    k_intrans<<<dim3(64, NB), 256>>>(y1, vv, 64);
    k_gemm<<<dim3(4, NB), 512, SMEMG>>>(vv, u2, conv2_b, (__half*)y2, 512, 64);

    k_final<<<NB, 256>>>((__half*)y2, wclsT, out);
}